// round 14
// baseline (speedup 1.0000x reference)
#include <cuda_runtime.h>

#define NSEQ 4096
#define DMODEL 1024

// Scratch (static device globals: allocation-free per harness rules)
__device__ float g_Q[NSEQ * DMODEL];
__device__ float g_K[NSEQ * DMODEL];
__device__ float g_V[NSEQ * DMODEL];
__device__ float g_S[(size_t)NSEQ * NSEQ];

#define BM 64
#define BN 64
#define BK 16

// ---------------------------------------------------------------------------
// Threefry2x32, exactly matching jax.random with seed 42.
// key(42) -> (k0, k1) = (0, 42)
// ---------------------------------------------------------------------------
__device__ __forceinline__ unsigned rotl32(unsigned v, int r) {
    return __funnelshift_l(v, v, r);
}

__device__ __forceinline__ void threefry_42(unsigned x0, unsigned x1,
                                            unsigned& o0, unsigned& o1)
{
    const unsigned ks0 = 0u;
    const unsigned ks1 = 42u;
    const unsigned ks2 = 0x1BD11BDAu ^ ks0 ^ ks1;
    x0 += ks0; x1 += ks1;
#define TF_R(r) { x0 += x1; x1 = rotl32(x1, (r)); x1 ^= x0; }
    TF_R(13) TF_R(15) TF_R(26) TF_R(6)
    x0 += ks1; x1 += ks2 + 1u;
    TF_R(17) TF_R(29) TF_R(16) TF_R(24)
    x0 += ks2; x1 += ks0 + 2u;
    TF_R(13) TF_R(15) TF_R(26) TF_R(6)
    x0 += ks0; x1 += ks1 + 3u;
    TF_R(17) TF_R(29) TF_R(16) TF_R(24)
    x0 += ks1; x1 += ks2 + 4u;
    TF_R(13) TF_R(15) TF_R(26) TF_R(6)
    x0 += ks2; x1 += ks0 + 5u;
#undef TF_R
    o0 = x0; o1 = x1;
}

// Partitionable-threefry random bits for element idx of a flat array:
// counter = iota(u64) -> bind key=(0,42), (counts_hi, counts_lo) = (0, idx).
// For bit_width == 32 the partitionable path returns bits1 ^ bits2.
__device__ __forceinline__ unsigned jax_random_bits_partitionable(unsigned idx)
{
    unsigned o0, o1;
    threefry_42(0u, idx, o0, o1);
    return o0 ^ o1;
}

// ---------------------------------------------------------------------------
// mma.sync tf32 helpers
// ---------------------------------------------------------------------------
__device__ __forceinline__ unsigned f2tf32(float f) {
    unsigned r;
    asm("cvt.rna.tf32.f32 %0, %1;" : "=r"(r) : "f"(f));
    return r;
}

__device__ __forceinline__ void mma_tf32(float c[4],
                                         unsigned a0, unsigned a1,
                                         unsigned a2, unsigned a3,
                                         unsigned b0, unsigned b1)
{
    asm volatile(
        "mma.sync.aligned.m16n8k8.row.col.f32.tf32.tf32.f32 "
        "{%0,%1,%2,%3}, {%4,%5,%6,%7}, {%8,%9}, {%0,%1,%2,%3};"
        : "+f"(c[0]), "+f"(c[1]), "+f"(c[2]), "+f"(c[3])
        : "r"(a0), "r"(a1), "r"(a2), "r"(a3), "r"(b0), "r"(b1));
}

#define SA 36  // smem row stride for 64x32 tiles: bank = (4*row+col)%32, conflict-free
#define SB 72  // smem row stride for 32x64 V tile: bank = (8*k+n)%32, conflict-free

// ---------------------------------------------------------------------------
// Fused QKV GEMM (NT, fp32 SIMT): C[4096,1024] = X @ W^T
// blockIdx.z selects (wq -> g_Q, wk -> g_K, wv -> g_V)
// ---------------------------------------------------------------------------
__global__ __launch_bounds__(256) void qkv_gemm(const float* __restrict__ A,
                                                const float* __restrict__ Wq,
                                                const float* __restrict__ Wk,
                                                const float* __restrict__ Wv)
{
    __shared__ float As[BK][BM + 1];
    __shared__ float Bs[BK][BN + 1];
    const int K = DMODEL, Ncols = DMODEL;
    int bm = blockIdx.y, bn = blockIdx.x, sel = blockIdx.z;
    const float* B = (sel == 0) ? Wq : ((sel == 1) ? Wk : Wv);
    float* C = (sel == 0) ? g_Q : ((sel == 1) ? g_K : g_V);

    int tid = threadIdx.x;
    int tx = tid & 15, ty = tid >> 4;
    int lrow = tid >> 2, lc4 = (tid & 3) << 2;

    const float* Ap = A + (size_t)(bm * BM + lrow) * K + lc4;
    const float* Bp = B + (size_t)(bn * BN + lrow) * K + lc4;

    float acc[4][4] = {};
    for (int k0 = 0; k0 < K; k0 += BK) {
        float4 av = *(const float4*)(Ap + k0);
        float4 bv = *(const float4*)(Bp + k0);
        As[lc4 + 0][lrow] = av.x; As[lc4 + 1][lrow] = av.y;
        As[lc4 + 2][lrow] = av.z; As[lc4 + 3][lrow] = av.w;
        Bs[lc4 + 0][lrow] = bv.x; Bs[lc4 + 1][lrow] = bv.y;
        Bs[lc4 + 2][lrow] = bv.z; Bs[lc4 + 3][lrow] = bv.w;
        __syncthreads();
#pragma unroll
        for (int k = 0; k < BK; k++) {
            float a[4], b[4];
#pragma unroll
            for (int i = 0; i < 4; i++) a[i] = As[k][ty * 4 + i];
#pragma unroll
            for (int j = 0; j < 4; j++) b[j] = Bs[k][tx * 4 + j];
#pragma unroll
            for (int i = 0; i < 4; i++)
#pragma unroll
                for (int j = 0; j < 4; j++)
                    acc[i][j] = fmaf(a[i], b[j], acc[i][j]);
        }
        __syncthreads();
    }
    float* Cp = C + (size_t)(bm * BM + ty * 4) * Ncols + bn * BN + tx * 4;
#pragma unroll
    for (int i = 0; i < 4; i++) {
        float4 v = make_float4(acc[i][0], acc[i][1], acc[i][2], acc[i][3]);
        *(float4*)(Cp + (size_t)i * Ncols) = v;
    }
}

// ---------------------------------------------------------------------------
// Scores GEMM via mma.sync tf32 (NT, causal-block-skipped): S = Q @ K^T
// 64x64 block, 128 threads (2x2 warps of 32x32), K chunks of 32.
// ---------------------------------------------------------------------------
__global__ __launch_bounds__(128) void score_gemm_tc()
{
    int bm = blockIdx.y, bn = blockIdx.x;
    if (bn > bm) return;  // strictly above diagonal: never read downstream

    __shared__ __align__(16) float As[64][SA];
    __shared__ __align__(16) float Bs[64][SA];
    int tid = threadIdx.x, lane = tid & 31, w = tid >> 5;
    int wm = (w >> 1) << 5, wn = (w & 1) << 5;
    int lr = lane >> 2, lc = lane & 3;

    float c[2][4][4] = {};

    const float* Ag = g_Q + (size_t)(bm * 64) * DMODEL;
    const float* Bg = g_K + (size_t)(bn * 64) * DMODEL;

    for (int k0 = 0; k0 < DMODEL; k0 += 32) {
#pragma unroll
        for (int i = 0; i < 4; i++) {
            int f4 = tid + i * 128;              // 0..511 = 64 rows x 8 float4
            int r = f4 >> 3, c4 = (f4 & 7) << 2;
            *(float4*)&As[r][c4] = *(const float4*)(Ag + (size_t)r * DMODEL + k0 + c4);
            *(float4*)&Bs[r][c4] = *(const float4*)(Bg + (size_t)r * DMODEL + k0 + c4);
        }
        __syncthreads();
#pragma unroll
        for (int kk = 0; kk < 32; kk += 8) {
            unsigned a[2][4], b[4][2];
#pragma unroll
            for (int mi = 0; mi < 2; mi++) {
                int mb = wm + mi * 16;
                a[mi][0] = f2tf32(As[mb + lr][kk + lc]);
                a[mi][1] = f2tf32(As[mb + 8 + lr][kk + lc]);
                a[mi][2] = f2tf32(As[mb + lr][kk + 4 + lc]);
                a[mi][3] = f2tf32(As[mb + 8 + lr][kk + 4 + lc]);
            }
#pragma unroll
            for (int ni = 0; ni < 4; ni++) {
                int nb = wn + ni * 8;
                b[ni][0] = f2tf32(Bs[nb + lr][kk + lc]);      // B^T row n = K row n
                b[ni][1] = f2tf32(Bs[nb + lr][kk + 4 + lc]);
            }
#pragma unroll
            for (int mi = 0; mi < 2; mi++)
#pragma unroll
                for (int ni = 0; ni < 4; ni++)
                    mma_tf32(c[mi][ni], a[mi][0], a[mi][1], a[mi][2], a[mi][3],
                             b[ni][0], b[ni][1]);
        }
        __syncthreads();
    }
    float* Crow = g_S + (size_t)(bm * 64) * NSEQ + bn * 64;
#pragma unroll
    for (int mi = 0; mi < 2; mi++)
#pragma unroll
        for (int ni = 0; ni < 4; ni++) {
            int m = wm + mi * 16 + lr;
            int n = wn + ni * 8 + 2 * lc;
            float* p = Crow + (size_t)m * NSEQ + n;
            p[0] = c[mi][ni][0]; p[1] = c[mi][ni][1];
            float* p2 = p + (size_t)8 * NSEQ;
            p2[0] = c[mi][ni][2]; p2[1] = c[mi][ni][3];
        }
}

// ---------------------------------------------------------------------------
// Row softmax (scale 1/32, causal) + JAX-exact threefry dropout (p_keep=0.9),
// partitionable-threefry mapping. One block per row. Zero-fills [len, pad).
// ---------------------------------------------------------------------------
__global__ __launch_bounds__(256) void softmax_dropout()
{
    int i = blockIdx.x;
    float* row = g_S + (size_t)i * NSEQ;
    int len = i + 1;
    int pad = ((i >> 6) + 1) << 6;
    int t = threadIdx.x;
    __shared__ float red[256];

    // pass 1: max
    float mx = -3.4e38f;
    for (int j = t; j < len; j += 256) mx = fmaxf(mx, row[j]);
    red[t] = mx; __syncthreads();
    for (int s = 128; s > 0; s >>= 1) {
        if (t < s) red[t] = fmaxf(red[t], red[t + s]);
        __syncthreads();
    }
    mx = red[0];
    __syncthreads();

    // pass 2: exp + sum (store exp in place)
    const float inv = 1.0f / 32.0f;
    float sum = 0.0f;
    for (int j = t; j < len; j += 256) {
        float e = expf((row[j] - mx) * inv);
        row[j] = e;
        sum += e;
    }
    red[t] = sum; __syncthreads();
    for (int s = 128; s > 0; s >>= 1) {
        if (t < s) red[t] += red[t + s];
        __syncthreads();
    }
    float invSum = 1.0f / red[0];

    // pass 3: normalize + dropout (partitionable threefry: counter=(0, idx))
    for (int j = t; j < len; j += 256) {
        unsigned idx = (unsigned)i * (unsigned)NSEQ + (unsigned)j;  // flat row-major
        unsigned bits = jax_random_bits_partitionable(idx);
        float u = __uint_as_float((bits >> 9) | 0x3F800000u) - 1.0f;
        float w = row[j] * invSum;
        row[j] = (u < 0.9f) ? (w / 0.9f) : 0.0f;
    }
    // zero the diagonal-block padding so out_gemm can read k < (bi+1)*64
    for (int j = len + t; j < pad; j += 256) row[j] = 0.0f;
}

// ---------------------------------------------------------------------------
// Output GEMM via mma.sync tf32 (NN, causal k-limit): O = S @ V
// 64x64 block, 128 threads (2x2 warps of 32x32), K chunks of 32.
// ---------------------------------------------------------------------------
__global__ __launch_bounds__(128) void out_gemm_tc(float* __restrict__ Cout)
{
    int bm = blockIdx.y, bn = blockIdx.x;
    __shared__ __align__(16) float As[64][SA];   // P tile 64x32
    __shared__ __align__(16) float Bs[32][SB];   // V tile 32x64
    int tid = threadIdx.x, lane = tid & 31, w = tid >> 5;
    int wm = (w >> 1) << 5, wn = (w & 1) << 5;
    int lr = lane >> 2, lc = lane & 3;

    float c[2][4][4] = {};

    const float* Ag = g_S + (size_t)(bm * 64) * NSEQ;
    const float* Bg = g_V + bn * 64;
    int kmax = (bm + 1) * 64;  // causal: weights zero beyond this (padding zeroed)

    for (int k0 = 0; k0 < kmax; k0 += 32) {
#pragma unroll
        for (int i = 0; i < 4; i++) {
            int f4 = tid + i * 128;               // 0..511
            int r = f4 >> 3, c4 = (f4 & 7) << 2;  // A: 64 rows x 8 f4
            *(float4*)&As[r][c4] = *(const float4*)(Ag + (size_t)r * NSEQ + k0 + c4);
            int rb = f4 >> 4, cb4 = (f4 & 15) << 2;  // B: 32 rows x 16 f4
            *(float4*)&Bs[rb][cb4] = *(const float4*)(Bg + (size_t)(k0 + rb) * DMODEL + cb4);
        }
        __syncthreads();
#pragma unroll
        for (int kk = 0; kk < 32; kk += 8) {
            unsigned a[2][4], b[4][2];
#pragma unroll
            for (int mi = 0; mi < 2; mi++) {
                int mb = wm + mi * 16;
                a[mi][0] = f2tf32(As[mb + lr][kk + lc]);
                a[mi][1] = f2tf32(As[mb + 8 + lr][kk + lc]);
                a[mi][2] = f2tf32(As[mb + lr][kk + 4 + lc]);
                a[mi][3] = f2tf32(As[mb + 8 + lr][kk + 4 + lc]);
            }
#pragma unroll
            for (int ni = 0; ni < 4; ni++) {
                int nb = wn + ni * 8;
                b[ni][0] = f2tf32(Bs[kk + lc][nb + lr]);       // V[k][n]
                b[ni][1] = f2tf32(Bs[kk + 4 + lc][nb + lr]);
            }
#pragma unroll
            for (int mi = 0; mi < 2; mi++)
#pragma unroll
                for (int ni = 0; ni < 4; ni++)
                    mma_tf32(c[mi][ni], a[mi][0], a[mi][1], a[mi][2], a[mi][3],
                             b[ni][0], b[ni][1]);
        }
        __syncthreads();
    }
    float* Crow = Cout + (size_t)(bm * 64) * DMODEL + bn * 64;
#pragma unroll
    for (int mi = 0; mi < 2; mi++)
#pragma unroll
        for (int ni = 0; ni < 4; ni++) {
            int m = wm + mi * 16 + lr;
            int n = wn + ni * 8 + 2 * lc;
            float* p = Crow + (size_t)m * DMODEL + n;
            p[0] = c[mi][ni][0]; p[1] = c[mi][ni][1];
            float* p2 = p + (size_t)8 * DMODEL;
            p2[0] = c[mi][ni][2]; p2[1] = c[mi][ni][3];
        }
}

// ---------------------------------------------------------------------------
extern "C" void kernel_launch(void* const* d_in, const int* in_sizes, int n_in,
                              void* d_out, int out_size)
{
    const float* x  = (const float*)d_in[0];
    const float* wq = (const float*)d_in[1];
    const float* wk = (const float*)d_in[2];
    const float* wv = (const float*)d_in[3];
    float* out = (float*)d_out;

    dim3 grid_qkv(DMODEL / BN, NSEQ / BM, 3);  // (16, 64, 3)
    dim3 grid_s(NSEQ / 64, NSEQ / 64);         // (64, 64), upper blocks early-out
    dim3 grid_o(DMODEL / 64, NSEQ / 64);       // (16, 64)

    qkv_gemm<<<grid_qkv, 256>>>(x, wq, wk, wv);
    score_gemm_tc<<<grid_s, 128>>>();
    softmax_dropout<<<NSEQ, 256>>>();
    out_gemm_tc<<<grid_o, 128>>>(out);
}

// round 15
// speedup vs baseline: 2.0629x; 2.0629x over previous
#include <cuda_runtime.h>

#define NSEQ 4096
#define DMODEL 1024

// Scratch (static device globals: allocation-free per harness rules)
__device__ float g_Q[NSEQ * DMODEL];
__device__ float g_K[NSEQ * DMODEL];
__device__ float g_V[NSEQ * DMODEL];
__device__ float g_S[(size_t)NSEQ * NSEQ];

// ---------------------------------------------------------------------------
// Threefry2x32, exactly matching jax.random with seed 42 (hardware-proven R14).
// ---------------------------------------------------------------------------
__device__ __forceinline__ unsigned rotl32(unsigned v, int r) {
    return __funnelshift_l(v, v, r);
}

__device__ __forceinline__ void threefry_42(unsigned x0, unsigned x1,
                                            unsigned& o0, unsigned& o1)
{
    const unsigned ks0 = 0u;
    const unsigned ks1 = 42u;
    const unsigned ks2 = 0x1BD11BDAu ^ ks0 ^ ks1;
    x0 += ks0; x1 += ks1;
#define TF_R(r) { x0 += x1; x1 = rotl32(x1, (r)); x1 ^= x0; }
    TF_R(13) TF_R(15) TF_R(26) TF_R(6)
    x0 += ks1; x1 += ks2 + 1u;
    TF_R(17) TF_R(29) TF_R(16) TF_R(24)
    x0 += ks2; x1 += ks0 + 2u;
    TF_R(13) TF_R(15) TF_R(26) TF_R(6)
    x0 += ks0; x1 += ks1 + 3u;
    TF_R(17) TF_R(29) TF_R(16) TF_R(24)
    x0 += ks1; x1 += ks2 + 4u;
    TF_R(13) TF_R(15) TF_R(26) TF_R(6)
    x0 += ks2; x1 += ks0 + 5u;
#undef TF_R
    o0 = x0; o1 = x1;
}

__device__ __forceinline__ unsigned jax_random_bits_partitionable(unsigned idx)
{
    unsigned o0, o1;
    threefry_42(0u, idx, o0, o1);
    return o0 ^ o1;
}

// ---------------------------------------------------------------------------
// mma.sync tf32 helpers
// ---------------------------------------------------------------------------
__device__ __forceinline__ unsigned f2tf32(float f) {
    unsigned r;
    asm("cvt.rna.tf32.f32 %0, %1;" : "=r"(r) : "f"(f));
    return r;
}

__device__ __forceinline__ void mma_tf32(float c[4],
                                         unsigned a0, unsigned a1,
                                         unsigned a2, unsigned a3,
                                         unsigned b0, unsigned b1)
{
    asm volatile(
        "mma.sync.aligned.m16n8k8.row.col.f32.tf32.tf32.f32 "
        "{%0,%1,%2,%3}, {%4,%5,%6,%7}, {%8,%9}, {%0,%1,%2,%3};"
        : "+f"(c[0]), "+f"(c[1]), "+f"(c[2]), "+f"(c[3])
        : "r"(a0), "r"(a1), "r"(a2), "r"(a3), "r"(b0), "r"(b1));
}

#define SA 36  // smem row stride (words) for 64x32 tiles: bank=(4*row+col)%32, conflict-free
#define SB 72  // smem row stride (words) for 32x64 V tile: bank=(8*k+n)%32, conflict-free

// ---------------------------------------------------------------------------
// QKV GEMM via mma.sync tf32 (NT): C[4096,1024] = X @ W^T
// Structure cloned from the hardware-proven score_gemm_tc. tf32 conversion
// happens ONCE at smem fill; inner loop is pure LDS + mma.
// blockIdx.z selects (wq -> g_Q, wk -> g_K, wv -> g_V)
// ---------------------------------------------------------------------------
__global__ __launch_bounds__(128) void qkv_gemm_tc(const float* __restrict__ A,
                                                   const float* __restrict__ Wq,
                                                   const float* __restrict__ Wk,
                                                   const float* __restrict__ Wv)
{
    int bm = blockIdx.y, bn = blockIdx.x, sel = blockIdx.z;
    const float* B = (sel == 0) ? Wq : ((sel == 1) ? Wk : Wv);
    float* C = (sel == 0) ? g_Q : ((sel == 1) ? g_K : g_V);

    __shared__ __align__(16) unsigned As[64][SA];
    __shared__ __align__(16) unsigned Bs[64][SA];
    int tid = threadIdx.x, lane = tid & 31, w = tid >> 5;
    int wm = (w >> 1) << 5, wn = (w & 1) << 5;
    int lr = lane >> 2, lc = lane & 3;

    float c[2][4][4] = {};

    const float* Ag = A + (size_t)(bm * 64) * DMODEL;
    const float* Bg = B + (size_t)(bn * 64) * DMODEL;

    for (int k0 = 0; k0 < DMODEL; k0 += 32) {
#pragma unroll
        for (int i = 0; i < 4; i++) {
            int f4 = tid + i * 128;              // 0..511 = 64 rows x 8 float4
            int r = f4 >> 3, c4 = (f4 & 7) << 2;
            float4 av = *(const float4*)(Ag + (size_t)r * DMODEL + k0 + c4);
            float4 bv = *(const float4*)(Bg + (size_t)r * DMODEL + k0 + c4);
            uint4 ua = make_uint4(f2tf32(av.x), f2tf32(av.y), f2tf32(av.z), f2tf32(av.w));
            uint4 ub = make_uint4(f2tf32(bv.x), f2tf32(bv.y), f2tf32(bv.z), f2tf32(bv.w));
            *(uint4*)&As[r][c4] = ua;
            *(uint4*)&Bs[r][c4] = ub;
        }
        __syncthreads();
#pragma unroll
        for (int kk = 0; kk < 32; kk += 8) {
            unsigned a[2][4], b[4][2];
#pragma unroll
            for (int mi = 0; mi < 2; mi++) {
                int mb = wm + mi * 16;
                a[mi][0] = As[mb + lr][kk + lc];
                a[mi][1] = As[mb + 8 + lr][kk + lc];
                a[mi][2] = As[mb + lr][kk + 4 + lc];
                a[mi][3] = As[mb + 8 + lr][kk + 4 + lc];
            }
#pragma unroll
            for (int ni = 0; ni < 4; ni++) {
                int nb = wn + ni * 8;
                b[ni][0] = Bs[nb + lr][kk + lc];
                b[ni][1] = Bs[nb + lr][kk + 4 + lc];
            }
#pragma unroll
            for (int mi = 0; mi < 2; mi++)
#pragma unroll
                for (int ni = 0; ni < 4; ni++)
                    mma_tf32(c[mi][ni], a[mi][0], a[mi][1], a[mi][2], a[mi][3],
                             b[ni][0], b[ni][1]);
        }
        __syncthreads();
    }
    float* Crow = C + (size_t)(bm * 64) * DMODEL + bn * 64;
#pragma unroll
    for (int mi = 0; mi < 2; mi++)
#pragma unroll
        for (int ni = 0; ni < 4; ni++) {
            int m = wm + mi * 16 + lr;
            int n = wn + ni * 8 + 2 * lc;
            float* p = Crow + (size_t)m * DMODEL + n;
            p[0] = c[mi][ni][0]; p[1] = c[mi][ni][1];
            float* p2 = p + (size_t)8 * DMODEL;
            p2[0] = c[mi][ni][2]; p2[1] = c[mi][ni][3];
        }
}

// ---------------------------------------------------------------------------
// Scores GEMM via mma.sync tf32 (NT, causal-block-skipped): S = Q @ K^T
// tf32 cvt at fill; inner loop pure LDS + mma.
// ---------------------------------------------------------------------------
__global__ __launch_bounds__(128) void score_gemm_tc()
{
    int bm = blockIdx.y, bn = blockIdx.x;
    if (bn > bm) return;  // strictly above diagonal: never read downstream

    __shared__ __align__(16) unsigned As[64][SA];
    __shared__ __align__(16) unsigned Bs[64][SA];
    int tid = threadIdx.x, lane = tid & 31, w = tid >> 5;
    int wm = (w >> 1) << 5, wn = (w & 1) << 5;
    int lr = lane >> 2, lc = lane & 3;

    float c[2][4][4] = {};

    const float* Ag = g_Q + (size_t)(bm * 64) * DMODEL;
    const float* Bg = g_K + (size_t)(bn * 64) * DMODEL;

    for (int k0 = 0; k0 < DMODEL; k0 += 32) {
#pragma unroll
        for (int i = 0; i < 4; i++) {
            int f4 = tid + i * 128;              // 0..511 = 64 rows x 8 float4
            int r = f4 >> 3, c4 = (f4 & 7) << 2;
            float4 av = *(const float4*)(Ag + (size_t)r * DMODEL + k0 + c4);
            float4 bv = *(const float4*)(Bg + (size_t)r * DMODEL + k0 + c4);
            uint4 ua = make_uint4(f2tf32(av.x), f2tf32(av.y), f2tf32(av.z), f2tf32(av.w));
            uint4 ub = make_uint4(f2tf32(bv.x), f2tf32(bv.y), f2tf32(bv.z), f2tf32(bv.w));
            *(uint4*)&As[r][c4] = ua;
            *(uint4*)&Bs[r][c4] = ub;
        }
        __syncthreads();
#pragma unroll
        for (int kk = 0; kk < 32; kk += 8) {
            unsigned a[2][4], b[4][2];
#pragma unroll
            for (int mi = 0; mi < 2; mi++) {
                int mb = wm + mi * 16;
                a[mi][0] = As[mb + lr][kk + lc];
                a[mi][1] = As[mb + 8 + lr][kk + lc];
                a[mi][2] = As[mb + lr][kk + 4 + lc];
                a[mi][3] = As[mb + 8 + lr][kk + 4 + lc];
            }
#pragma unroll
            for (int ni = 0; ni < 4; ni++) {
                int nb = wn + ni * 8;
                b[ni][0] = Bs[nb + lr][kk + lc];      // B^T row n = K row n
                b[ni][1] = Bs[nb + lr][kk + 4 + lc];
            }
#pragma unroll
            for (int mi = 0; mi < 2; mi++)
#pragma unroll
                for (int ni = 0; ni < 4; ni++)
                    mma_tf32(c[mi][ni], a[mi][0], a[mi][1], a[mi][2], a[mi][3],
                             b[ni][0], b[ni][1]);
        }
        __syncthreads();
    }
    float* Crow = g_S + (size_t)(bm * 64) * NSEQ + bn * 64;
#pragma unroll
    for (int mi = 0; mi < 2; mi++)
#pragma unroll
        for (int ni = 0; ni < 4; ni++) {
            int m = wm + mi * 16 + lr;
            int n = wn + ni * 8 + 2 * lc;
            float* p = Crow + (size_t)m * NSEQ + n;
            p[0] = c[mi][ni][0]; p[1] = c[mi][ni][1];
            float* p2 = p + (size_t)8 * NSEQ;
            p2[0] = c[mi][ni][2]; p2[1] = c[mi][ni][3];
        }
}

// ---------------------------------------------------------------------------
// Row softmax (scale 1/32, causal) + JAX-exact threefry dropout (p_keep=0.9),
// partitionable-threefry mapping (hardware-proven R14).
// ---------------------------------------------------------------------------
__global__ __launch_bounds__(256) void softmax_dropout()
{
    int i = blockIdx.x;
    float* row = g_S + (size_t)i * NSEQ;
    int len = i + 1;
    int pad = ((i >> 6) + 1) << 6;
    int t = threadIdx.x;
    __shared__ float red[256];

    // pass 1: max
    float mx = -3.4e38f;
    for (int j = t; j < len; j += 256) mx = fmaxf(mx, row[j]);
    red[t] = mx; __syncthreads();
    for (int s = 128; s > 0; s >>= 1) {
        if (t < s) red[t] = fmaxf(red[t], red[t + s]);
        __syncthreads();
    }
    mx = red[0];
    __syncthreads();

    // pass 2: exp + sum (store exp in place)
    const float inv = 1.0f / 32.0f;
    float sum = 0.0f;
    for (int j = t; j < len; j += 256) {
        float e = expf((row[j] - mx) * inv);
        row[j] = e;
        sum += e;
    }
    red[t] = sum; __syncthreads();
    for (int s = 128; s > 0; s >>= 1) {
        if (t < s) red[t] += red[t + s];
        __syncthreads();
    }
    float invSum = 1.0f / red[0];

    // pass 3: normalize + dropout (partitionable threefry: counter=(0, idx))
    for (int j = t; j < len; j += 256) {
        unsigned idx = (unsigned)i * (unsigned)NSEQ + (unsigned)j;  // flat row-major
        unsigned bits = jax_random_bits_partitionable(idx);
        float u = __uint_as_float((bits >> 9) | 0x3F800000u) - 1.0f;
        float w = row[j] * invSum;
        row[j] = (u < 0.9f) ? (w / 0.9f) : 0.0f;
    }
    // zero the diagonal-block padding so out_gemm can read k < (bi+1)*64
    for (int j = len + t; j < pad; j += 256) row[j] = 0.0f;
}

// ---------------------------------------------------------------------------
// Output GEMM via mma.sync tf32 (NN, causal k-limit): O = S @ V
// tf32 cvt at fill; inner loop pure LDS + mma.
// ---------------------------------------------------------------------------
__global__ __launch_bounds__(128) void out_gemm_tc(float* __restrict__ Cout)
{
    int bm = blockIdx.y, bn = blockIdx.x;
    __shared__ __align__(16) unsigned As[64][SA];   // P tile 64x32
    __shared__ __align__(16) unsigned Bs[32][SB];   // V tile 32x64
    int tid = threadIdx.x, lane = tid & 31, w = tid >> 5;
    int wm = (w >> 1) << 5, wn = (w & 1) << 5;
    int lr = lane >> 2, lc = lane & 3;

    float c[2][4][4] = {};

    const float* Ag = g_S + (size_t)(bm * 64) * NSEQ;
    const float* Bg = g_V + bn * 64;
    int kmax = (bm + 1) * 64;  // causal: weights zero beyond this (padding zeroed)

    for (int k0 = 0; k0 < kmax; k0 += 32) {
#pragma unroll
        for (int i = 0; i < 4; i++) {
            int f4 = tid + i * 128;               // 0..511
            int r = f4 >> 3, c4 = (f4 & 7) << 2;  // A: 64 rows x 8 f4
            float4 av = *(const float4*)(Ag + (size_t)r * NSEQ + k0 + c4);
            uint4 ua = make_uint4(f2tf32(av.x), f2tf32(av.y), f2tf32(av.z), f2tf32(av.w));
            *(uint4*)&As[r][c4] = ua;
            int rb = f4 >> 4, cb4 = (f4 & 15) << 2;  // B: 32 rows x 16 f4
            float4 bv = *(const float4*)(Bg + (size_t)(k0 + rb) * DMODEL + cb4);
            uint4 ub = make_uint4(f2tf32(bv.x), f2tf32(bv.y), f2tf32(bv.z), f2tf32(bv.w));
            *(uint4*)&Bs[rb][cb4] = ub;
        }
        __syncthreads();
#pragma unroll
        for (int kk = 0; kk < 32; kk += 8) {
            unsigned a[2][4], b[4][2];
#pragma unroll
            for (int mi = 0; mi < 2; mi++) {
                int mb = wm + mi * 16;
                a[mi][0] = As[mb + lr][kk + lc];
                a[mi][1] = As[mb + 8 + lr][kk + lc];
                a[mi][2] = As[mb + lr][kk + 4 + lc];
                a[mi][3] = As[mb + 8 + lr][kk + 4 + lc];
            }
#pragma unroll
            for (int ni = 0; ni < 4; ni++) {
                int nb = wn + ni * 8;
                b[ni][0] = Bs[kk + lc][nb + lr];       // V[k][n]
                b[ni][1] = Bs[kk + 4 + lc][nb + lr];
            }
#pragma unroll
            for (int mi = 0; mi < 2; mi++)
#pragma unroll
                for (int ni = 0; ni < 4; ni++)
                    mma_tf32(c[mi][ni], a[mi][0], a[mi][1], a[mi][2], a[mi][3],
                             b[ni][0], b[ni][1]);
        }
        __syncthreads();
    }
    float* Crow = Cout + (size_t)(bm * 64) * DMODEL + bn * 64;
#pragma unroll
    for (int mi = 0; mi < 2; mi++)
#pragma unroll
        for (int ni = 0; ni < 4; ni++) {
            int m = wm + mi * 16 + lr;
            int n = wn + ni * 8 + 2 * lc;
            float* p = Crow + (size_t)m * DMODEL + n;
            p[0] = c[mi][ni][0]; p[1] = c[mi][ni][1];
            float* p2 = p + (size_t)8 * DMODEL;
            p2[0] = c[mi][ni][2]; p2[1] = c[mi][ni][3];
        }
}

// ---------------------------------------------------------------------------
extern "C" void kernel_launch(void* const* d_in, const int* in_sizes, int n_in,
                              void* d_out, int out_size)
{
    const float* x  = (const float*)d_in[0];
    const float* wq = (const float*)d_in[1];
    const float* wk = (const float*)d_in[2];
    const float* wv = (const float*)d_in[3];
    float* out = (float*)d_out;

    dim3 grid_qkv(DMODEL / 64, NSEQ / 64, 3);  // (16, 64, 3)
    dim3 grid_s(NSEQ / 64, NSEQ / 64);         // (64, 64), upper blocks early-out
    dim3 grid_o(DMODEL / 64, NSEQ / 64);       // (16, 64)

    qkv_gemm_tc<<<grid_qkv, 128>>>(x, wq, wk, wv);
    score_gemm_tc<<<grid_s, 128>>>();
    softmax_dropout<<<NSEQ, 256>>>();
    out_gemm_tc<<<grid_o, 128>>>(out);
}